// round 8
// baseline (speedup 1.0000x reference)
#include <cuda_runtime.h>

// CrossAttention_47502338294587 — algebraic collapse:
// K/V come from one per-batch visual token broadcast over T -> every logit row
// is constant -> softmax exactly uniform -> y == v.
// out[b,t,:] = ((vf @ Wv + bv) @ Wp + bp)[b,:]   (independent of x, Wq, Wk).
//
// ONE persistent kernel, grid 256 (proven deadlock-safe in R7), 2 barriers:
//  A : CTA (cg,ks) -> partials of vf@Wv          (Wv read ONCE, 4 LDG.128/thr)
//  B : CTA (cg,ks) -> fold vv tile, partials of vv@Wp (Wp read ONCE — the R7
//      version read it 8x redundantly, 32MB L2 traffic -> this was the 15us)
//  C : CTA (b,cg,th) -> fold row slice, broadcast-write 512 t-rows (STG.128)

static constexpr int C    = 1024;
static constexpr int B    = 4;
static constexpr int T    = 1024;
static constexpr int KS   = 8;       // k-splits (128 k-rows per CTA)
static constexpr int GRID = 256;

__device__ float    g_part1[KS * B * C];   // 128 KB (L2-resident)
__device__ float    g_part2[KS * B * C];   // 128 KB
__device__ unsigned g_cnt   = 0;           // barrier arrivals (self-resetting)
__device__ unsigned g_epoch = 0;           // barrier releases (monotonic)

__device__ __forceinline__ void grid_barrier(int t, unsigned expect)
{
    if (t == 0) {
        const unsigned old = atomicAdd(&g_cnt, 1);
        if (old == GRID - 1) {
            g_cnt = 0;                       // reset BEFORE release
            __threadfence();
            atomicAdd(&g_epoch, 1);
        } else {
            while (*(volatile unsigned*)&g_epoch == expect) __nanosleep(32);
        }
        __threadfence();
    }
    __syncthreads();
}

__global__ void __launch_bounds__(256, 4) fused_kernel(
    const float* __restrict__ vf,   // [B][C]
    const float* __restrict__ Wv,   // [C][C]
    const float* __restrict__ bv,   // [C]
    const float* __restrict__ Wp,   // [C][C]
    const float* __restrict__ bp,   // [C]
    float* __restrict__ out)        // [B][T][C]
{
    __shared__ float  s_in[B][128];    // 2 KB  (vf tile / vv tile)
    __shared__ float4 s_red[256][B];   // 16 KB
    __shared__ float  s_rowf[32];

    const int t  = threadIdx.x;
    const int f4 = t & 7;              // float4 column within 32-col group
    const int kr = t >> 3;             // 0..31

    const int cg = blockIdx.x & 31;    // 0..31 column group (A and B phases)
    const int ks = blockIdx.x >> 5;    // 0..7  k-split
    const int k0 = ks * 128;

    // Epoch read before any CTA can release barrier 1 (needs ALL arrivals).
    const unsigned e0 = *(volatile unsigned*)&g_epoch;

    // ============ Phase A: partials of vf @ Wv (Wv read once) ============
    {
        const float4* W4 = (const float4*)Wv;
        float4 w[4];
        #pragma unroll
        for (int i = 0; i < 4; i++)          // 4 independent full-line LDG.128
            w[i] = W4[(size_t)(k0 + kr + 32 * i) * 256 + cg * 8 + f4];

        #pragma unroll
        for (int i = 0; i < 2; i++) {        // stage vf k-tile (512 values)
            const int e = t + 256 * i;
            s_in[e >> 7][e & 127] = vf[(e >> 7) * C + k0 + (e & 127)];
        }
        __syncthreads();

        #pragma unroll
        for (int b = 0; b < B; b++) {
            float4 a = make_float4(0.f, 0.f, 0.f, 0.f);
            #pragma unroll
            for (int i = 0; i < 4; i++) {
                const float s = s_in[b][kr + 32 * i];
                a.x = fmaf(s, w[i].x, a.x);
                a.y = fmaf(s, w[i].y, a.y);
                a.z = fmaf(s, w[i].z, a.z);
                a.w = fmaf(s, w[i].w, a.w);
            }
            s_red[t][b] = a;
        }
        __syncthreads();

        #pragma unroll
        for (int off = 16; off > 0; off >>= 1) {   // reduce over kr
            if (kr < off) {
                #pragma unroll
                for (int b = 0; b < B; b++) {
                    float4 a = s_red[t][b];
                    const float4 o = s_red[t + off * 8][b];
                    a.x += o.x; a.y += o.y; a.z += o.z; a.w += o.w;
                    s_red[t][b] = a;
                }
            }
            __syncthreads();
        }

        if (t < 8) {
            #pragma unroll
            for (int b = 0; b < B; b++)
                ((float4*)g_part1)[(ks * B + b) * 256 + cg * 8 + t] = s_red[t][b];
            __threadfence();               // publish before arriving
        }
        __syncthreads();
    }

    grid_barrier(t, e0);                   // ---- barrier 1 ----

    // ======= Phase B: partials of vv @ Wp (same (cg,ks) split, Wp once) =======
    {
        const float4* W4 = (const float4*)Wp;
        float4 w[4];
        #pragma unroll
        for (int i = 0; i < 4; i++)          // issue W loads first
            w[i] = W4[(size_t)(k0 + kr + 32 * i) * 256 + cg * 8 + f4];

        #pragma unroll
        for (int i = 0; i < 2; i++) {        // fold vv k-tile from part1 (+bv)
            const int e  = t + 256 * i;
            const int b  = e >> 7;
            const int kk = e & 127;
            float v = bv[k0 + kk];
            #pragma unroll
            for (int s = 0; s < KS; s++)
                v += __ldcg(&g_part1[(s * B + b) * C + k0 + kk]);
            s_in[b][kk] = v;
        }
        __syncthreads();

        #pragma unroll
        for (int b = 0; b < B; b++) {
            float4 a = make_float4(0.f, 0.f, 0.f, 0.f);
            #pragma unroll
            for (int i = 0; i < 4; i++) {
                const float s = s_in[b][kr + 32 * i];
                a.x = fmaf(s, w[i].x, a.x);
                a.y = fmaf(s, w[i].y, a.y);
                a.z = fmaf(s, w[i].z, a.z);
                a.w = fmaf(s, w[i].w, a.w);
            }
            s_red[t][b] = a;
        }
        __syncthreads();

        #pragma unroll
        for (int off = 16; off > 0; off >>= 1) {
            if (kr < off) {
                #pragma unroll
                for (int b = 0; b < B; b++) {
                    float4 a = s_red[t][b];
                    const float4 o = s_red[t + off * 8][b];
                    a.x += o.x; a.y += o.y; a.z += o.z; a.w += o.w;
                    s_red[t][b] = a;
                }
            }
            __syncthreads();
        }

        if (t < 8) {
            #pragma unroll
            for (int b = 0; b < B; b++)
                ((float4*)g_part2)[(ks * B + b) * 256 + cg * 8 + t] = s_red[t][b];
            __threadfence();
        }
        __syncthreads();
    }

    grid_barrier(t, e0 + 1);               // ---- barrier 2 ----

    // ===== Phase C: fold row slice, broadcast-write (b, cg2, th) =====
    {
        const int b   = blockIdx.x >> 6;          // 0..3
        const int cg2 = (blockIdx.x >> 1) & 31;   // 0..31
        const int th  = blockIdx.x & 1;           // t-half

        if (t < 32) {
            const int c = cg2 * 32 + t;
            float v = bp[c];
            #pragma unroll
            for (int s = 0; s < KS; s++)
                v += __ldcg(&g_part2[(s * B + b) * C + c]);
            s_rowf[t] = v;
        }
        __syncthreads();

        const float4 r = ((const float4*)s_rowf)[f4];
        float4* o4 = (float4*)out;
        const size_t base = ((size_t)b * T + th * 512) * 256 + cg2 * 8 + f4;
        #pragma unroll
        for (int i = 0; i < 16; i++)              // rows kr, kr+32, ..., kr+480
            o4[base + (size_t)(kr + 32 * i) * 256] = r;
    }
}

extern "C" void kernel_launch(void* const* d_in, const int* in_sizes, int n_in,
                              void* d_out, int out_size)
{
    (void)in_sizes; (void)n_in; (void)out_size;
    const float* vf = (const float*)d_in[1];  // visual_features [B,C]
    const float* Wv = (const float*)d_in[6];
    const float* bv = (const float*)d_in[7];
    const float* Wp = (const float*)d_in[8];
    const float* bp = (const float*)d_in[9];
    float* out = (float*)d_out;

    fused_kernel<<<GRID, 256>>>(vf, Wv, bv, Wp, bp, out);
}

// round 9
// speedup vs baseline: 1.1214x; 1.1214x over previous
#include <cuda_runtime.h>

// CrossAttention_47502338294587 — algebraic collapse:
// K/V come from one per-batch visual token broadcast over T -> every logit row
// is constant -> softmax exactly uniform -> y == v.
// out[b,t,:] = ((vf @ Wv + bv) @ Wp + bp)[b,:]   (independent of x, Wq, Wk).
//
// ONE persistent kernel, grid 256. NO full-grid barriers (measured: each grid
// barrier cost ~2-4us of straggler alignment; R7 1-barrier=14.85, R8
// 2-barrier=18.9 despite 28MB less traffic). Instead: per-column-group
// dataflow flags -> consumers proceed as soon as THEIR producers finish,
// and Wp/bias loads are prefetched before the spin so DRAM latency overlaps.
//  A : CTA (cg,ks) -> partials of vf@Wv -> g_part1, flag cnt1[cg]
//  B : CTA (cg,ks) -> prefetch Wp tile, wait cnt1[4ks..4ks+3]==8,
//      fold vv k-tile, partials of vv@Wp -> g_part2, flag cnt2[cg]
//  C : CTA (b,cg2,th) -> prefetch bp, wait cnt2[cg2]==8, fold row slice,
//      broadcast-write 512 t-rows (full-line STG.128)
//  Reset: last-finishing CTA zeroes flags (replay-safe via stream ordering).

static constexpr int C    = 1024;
static constexpr int B    = 4;
static constexpr int T    = 1024;
static constexpr int KS   = 8;       // k-splits (128 k-rows per CTA)
static constexpr int GRID = 256;

__device__ float    g_part1[KS * B * C];   // 128 KB (L2-resident)
__device__ float    g_part2[KS * B * C];   // 128 KB
__device__ unsigned g_cnt1[32];            // part1 column-group ready counts
__device__ unsigned g_cnt2[32];            // part2 column-group ready counts
__device__ unsigned g_done = 0;

__device__ __forceinline__ void wait_count(volatile unsigned* p, unsigned target)
{
    while (*p < target) __nanosleep(64);
}

__global__ void __launch_bounds__(256, 4) fused_kernel(
    const float* __restrict__ vf,   // [B][C]
    const float* __restrict__ Wv,   // [C][C]
    const float* __restrict__ bv,   // [C]
    const float* __restrict__ Wp,   // [C][C]
    const float* __restrict__ bp,   // [C]
    float* __restrict__ out)        // [B][T][C]
{
    __shared__ float  s_in[B][128];    // 2 KB  (vf tile / vv tile)
    __shared__ float4 s_red[256][B];   // 16 KB
    __shared__ float  s_rowf[32];

    const int t  = threadIdx.x;
    const int f4 = t & 7;              // float4 column within 32-col group
    const int kr = t >> 3;             // 0..31

    const int cg = blockIdx.x & 31;    // 0..31 column group (phases A,B)
    const int ks = blockIdx.x >> 5;    // 0..7  k-split
    const int k0 = ks * 128;

    // ============ Phase A: partials of vf @ Wv (Wv read once) ============
    {
        const float4* W4 = (const float4*)Wv;
        float4 w[4];
        #pragma unroll
        for (int i = 0; i < 4; i++)          // 4 independent full-line LDG.128
            w[i] = W4[(size_t)(k0 + kr + 32 * i) * 256 + cg * 8 + f4];

        #pragma unroll
        for (int i = 0; i < 2; i++) {        // stage vf k-tile (512 values)
            const int e = t + 256 * i;
            s_in[e >> 7][e & 127] = vf[(e >> 7) * C + k0 + (e & 127)];
        }
        __syncthreads();

        #pragma unroll
        for (int b = 0; b < B; b++) {
            float4 a = make_float4(0.f, 0.f, 0.f, 0.f);
            #pragma unroll
            for (int i = 0; i < 4; i++) {
                const float s = s_in[b][kr + 32 * i];
                a.x = fmaf(s, w[i].x, a.x);
                a.y = fmaf(s, w[i].y, a.y);
                a.z = fmaf(s, w[i].z, a.z);
                a.w = fmaf(s, w[i].w, a.w);
            }
            s_red[t][b] = a;
        }
        __syncthreads();

        #pragma unroll
        for (int off = 16; off > 0; off >>= 1) {   // reduce over kr
            if (kr < off) {
                #pragma unroll
                for (int b = 0; b < B; b++) {
                    float4 a = s_red[t][b];
                    const float4 o = s_red[t + off * 8][b];
                    a.x += o.x; a.y += o.y; a.z += o.z; a.w += o.w;
                    s_red[t][b] = a;
                }
            }
            __syncthreads();
        }

        if (t < 8) {
            #pragma unroll
            for (int b = 0; b < B; b++)
                ((float4*)g_part1)[(ks * B + b) * 256 + cg * 8 + t] = s_red[t][b];
            __threadfence();               // publish tile before flagging
        }
        __syncthreads();
        if (t == 0) atomicAdd(&g_cnt1[cg], 1u);   // flag: this (cg,ks) tile done
    }

    // ======= Phase B: partials of vv @ Wp (same (cg,ks) split, Wp once) =======
    {
        const float4* W4 = (const float4*)Wp;
        float4 w[4];
        #pragma unroll
        for (int i = 0; i < 4; i++)          // PREFETCH Wp before waiting
            w[i] = W4[(size_t)(k0 + kr + 32 * i) * 256 + cg * 8 + f4];
        float bvv[2];
        #pragma unroll
        for (int i = 0; i < 2; i++) {        // prefetch bias too
            const int e = t + 256 * i;
            bvv[i] = bv[k0 + (e & 127)];
        }

        // wait only for OUR 4 producer column-groups (8 tiles each)
        if (t < 4) wait_count(&g_cnt1[4 * ks + t], KS);
        __syncthreads();
        __threadfence();                     // acquire part1 tiles

        #pragma unroll
        for (int i = 0; i < 2; i++) {        // fold vv k-tile (16 indep __ldcg)
            const int e  = t + 256 * i;
            const int b  = e >> 7;
            const int kk = e & 127;
            float v = bvv[i];
            #pragma unroll
            for (int s = 0; s < KS; s++)
                v += __ldcg(&g_part1[(s * B + b) * C + k0 + kk]);
            s_in[b][kk] = v;
        }
        __syncthreads();

        #pragma unroll
        for (int b = 0; b < B; b++) {
            float4 a = make_float4(0.f, 0.f, 0.f, 0.f);
            #pragma unroll
            for (int i = 0; i < 4; i++) {
                const float s = s_in[b][kr + 32 * i];
                a.x = fmaf(s, w[i].x, a.x);
                a.y = fmaf(s, w[i].y, a.y);
                a.z = fmaf(s, w[i].z, a.z);
                a.w = fmaf(s, w[i].w, a.w);
            }
            s_red[t][b] = a;
        }
        __syncthreads();

        #pragma unroll
        for (int off = 16; off > 0; off >>= 1) {
            if (kr < off) {
                #pragma unroll
                for (int b = 0; b < B; b++) {
                    float4 a = s_red[t][b];
                    const float4 o = s_red[t + off * 8][b];
                    a.x += o.x; a.y += o.y; a.z += o.z; a.w += o.w;
                    s_red[t][b] = a;
                }
            }
            __syncthreads();
        }

        if (t < 8) {
            #pragma unroll
            for (int b = 0; b < B; b++)
                ((float4*)g_part2)[(ks * B + b) * 256 + cg * 8 + t] = s_red[t][b];
            __threadfence();
        }
        __syncthreads();
        if (t == 0) atomicAdd(&g_cnt2[cg], 1u);
    }

    // ===== Phase C: fold row slice, broadcast-write (b, cg2, th) =====
    {
        const int b   = blockIdx.x >> 6;          // 0..3
        const int cg2 = (blockIdx.x >> 1) & 31;   // 0..31
        const int th  = blockIdx.x & 1;           // t-half

        float bpv = 0.f;
        if (t < 32) bpv = bp[cg2 * 32 + t];       // prefetch before wait

        if (t == 0) wait_count(&g_cnt2[cg2], KS); // wait for OUR column group
        __syncthreads();
        __threadfence();                          // acquire part2 tiles

        if (t < 32) {
            const int c = cg2 * 32 + t;
            float v = bpv;
            #pragma unroll
            for (int s = 0; s < KS; s++)
                v += __ldcg(&g_part2[(s * B + b) * C + c]);
            s_rowf[t] = v;
        }
        __syncthreads();

        const float4 r = ((const float4*)s_rowf)[f4];
        float4* o4 = (float4*)out;
        const size_t base = ((size_t)b * T + th * 512) * 256 + cg2 * 8 + f4;
        #pragma unroll
        for (int i = 0; i < 16; i++)              // rows kr, kr+32, ..., kr+480
            o4[base + (size_t)(kr + 32 * i) * 256] = r;
    }

    // ===== Replay-safe flag reset by the last CTA to finish =====
    __syncthreads();
    if (t == 0) {
        const unsigned d = atomicAdd(&g_done, 1u);
        if (d == GRID - 1) {                      // everyone else is done
            #pragma unroll
            for (int i = 0; i < 32; i++) { g_cnt1[i] = 0; g_cnt2[i] = 0; }
            __threadfence();
            g_done = 0;                           // visible to next replay
        }
    }
}

extern "C" void kernel_launch(void* const* d_in, const int* in_sizes, int n_in,
                              void* d_out, int out_size)
{
    (void)in_sizes; (void)n_in; (void)out_size;
    const float* vf = (const float*)d_in[1];  // visual_features [B,C]
    const float* Wv = (const float*)d_in[6];
    const float* bv = (const float*)d_in[7];
    const float* Wp = (const float*)d_in[8];
    const float* bp = (const float*)d_in[9];
    float* out = (float*)d_out;

    fused_kernel<<<GRID, 256>>>(vf, Wv, bv, Wp, bp, out);
}